// round 13
// baseline (speedup 1.0000x reference)
#include <cuda_runtime.h>
#include <cuda_bf16.h>

#define T_ 128
#define B_ 512
#define D_ 500
#define D4_ 125     // D/4 float4 per row
#define PF 8        // prefetch depth (rows ahead)
#define CPB 32      // columns per setup block
#define SSTR 132    // smem column stride (bytes): (l*33 + k) % 32 conflict-free

// Scratch (no allocation allowed): control-plane metadata.
// Meta byte per (b,t): bit0 = valid; bits[1:7] = (seg_to_emit_after_t + 1), 0 = none.
// Max emit value: lens <= 8 < token_len -> >=2 tokens/segment -> seg <= 64 -> (65<<1)|1 = 131 < 256.
__device__ unsigned int g_meta32[B_ * T_ / 4];
__device__ int g_newlen[B_];

// ---------------------------------------------------------------------------
// Kernel 1: SIMD-parallel greedy packing scans.
// 16 blocks x 128 threads, 32 columns per block. Warp w's lane l gathers
// column (c0+l), tokens t = r*4+w (coalesced 128B src reads per warp, all 32
// loads register-batched for full MLP). Then warp 0's 32 lanes run 32 scans
// IN LOCKSTEP (branchless -> no divergence): the serial dep chain is paid
// once per 32 columns instead of once per column, and launch/ramp overhead
// is amortized over 16 blocks instead of 512.
// ---------------------------------------------------------------------------
__global__ __launch_bounds__(128) void setup_kernel(const int* __restrict__ src,
                                                    const int* __restrict__ token_lengths,
                                                    const int* __restrict__ token_len_p)
{
    __shared__ unsigned char s_len [CPB * SSTR];
    __shared__ unsigned char s_meta[CPB * SSTR];

    int tid  = threadIdx.x;
    int lane = tid & 31;
    int w    = tid >> 5;            // 0..3
    int c0   = blockIdx.x * CPB;

    // Clear meta (|= pattern below).
    for (int k = tid; k < CPB * SSTR / 4; k += 128)
        ((unsigned int*)s_meta)[k] = 0u;

    // ---- coalesced gather, fully register-batched ----
    int sv[T_ / 4];                 // 32 tokens per thread: t = r*4 + w
    #pragma unroll
    for (int r = 0; r < T_ / 4; r++)
        sv[r] = __ldcg(&src[(r * 4 + w) * B_ + c0 + lane]);
    #pragma unroll
    for (int r = 0; r < T_ / 4; r++) {
        int s = sv[r];
        int l = (s == 1) ? 0 : ((s == 0) ? 4 : token_lengths[s]);
        s_len[lane * SSTR + r * 4 + w] = (unsigned char)l;
    }
    __syncthreads();

    // ---- 32 lockstep scans (warp 0 only), branchless ----
    if (tid < CPB) {
        int token_len = token_len_p ? token_len_p[0] : 20;
        const unsigned char* Lp = &s_len [tid * SSTR];
        unsigned char*       Mp = &s_meta[tid * SSTR];

        int seg = 0, curr = 0, last_t = 0;
        #pragma unroll 4
        for (int t = 0; t < T_; t++) {
            int ll = Lp[t];
            bool valid = (ll != 0);
            bool close = valid & (curr > 0) & (curr + ll > token_len);
            if (close) Mp[last_t] |= (unsigned char)((seg + 1) << 1);
            seg  += (int)close;
            curr  = close ? 0 : curr;
            if (valid) Mp[t] |= 1;
            curr  += valid ? ll : 0;
            last_t = valid ? t : last_t;
        }
        bool trail = (curr > 0);
        if (trail) Mp[last_t] |= (unsigned char)((seg + 1) << 1);
        seg += (int)trail;
        g_newlen[c0 + tid] = seg;
    }
    __syncthreads();

    // ---- coalesced meta writeback (4 threads per column, 8 uints each) ----
    {
        int col = tid >> 2;                    // 0..31
        int k0  = (tid & 3) * 8;               // uint index within column
        #pragma unroll
        for (int k = k0; k < k0 + 8; k++) {
            unsigned int v = *(const unsigned int*)(s_meta + col * SSTR + k * 4);
            g_meta32[(c0 + col) * (T_ / 4) + k] = v;
        }
    }
}

// ---------------------------------------------------------------------------
// Kernel 2 (data plane + rank): one block per SOURCE column b, 128 threads.
// Identical to the proven R12 streaming kernel (37.1us, DRAM 70.8%), with
// byte meta. Reads each input row ONCE: accumulate valid rows, write-through
// rows t>=L, flush the accumulator at segment-end flags. Traffic: 262 MB.
// ---------------------------------------------------------------------------
__global__ __launch_bounds__(T_) void merge_kernel(const float4* __restrict__ embv,
                                                   float4* __restrict__ outv,
                                                   float* __restrict__ out_len,
                                                   int write_len)
{
    __shared__ unsigned char s_meta[T_];
    __shared__ int s_warp[4];
    __shared__ int s_rank;

    int b = blockIdx.x;
    int i = threadIdx.x;

    const long stride = (long)B_ * D4_;        // float4s per t-slab
    bool active = (i < D4_);
    int  ic     = active ? i : (D4_ - 1);      // clamped: loads always valid
    long ibase  = (long)b * D4_ + ic;

    // ---- kick off prefetch pipeline first (deep MLP) ----
    float4 buf[PF];
    #pragma unroll
    for (int k = 0; k < PF; k++) buf[k] = embv[ibase + (long)k * stride];

    // ---- overlap: meta load + rank reduction while loads are in flight ----
    s_meta[i] = ((const unsigned char*)g_meta32)[b * T_ + i];

    int myl = g_newlen[b];
    const int4* len4 = (const int4*)g_newlen;  // 512 / 4 = 128 == blockDim
    int4 v4 = len4[i];
    int j = 4 * i;
    int cnt = 0;
    cnt += (v4.x > myl) || (v4.x == myl && (j + 0) < b);
    cnt += (v4.y > myl) || (v4.y == myl && (j + 1) < b);
    cnt += (v4.z > myl) || (v4.z == myl && (j + 2) < b);
    cnt += (v4.w > myl) || (v4.w == myl && (j + 3) < b);
    #pragma unroll
    for (int o = 16; o > 0; o >>= 1) cnt += __shfl_down_sync(0xFFFFFFFFu, cnt, o);
    if ((i & 31) == 0) s_warp[i >> 5] = cnt;
    __syncthreads();
    if (i == 0) {
        int rank = s_warp[0] + s_warp[1] + s_warp[2] + s_warp[3];
        s_rank = rank;
        if (write_len) out_len[rank] = (float)myl;
    }
    __syncthreads();

    int  bo    = s_rank;
    int  L     = myl;
    long obase = (long)bo * D4_ + i;

    // ---- streaming loop with 8-deep ring buffer ----
    float4 acc = make_float4(0.f, 0.f, 0.f, 0.f);

    for (int to = 0; to < T_; to += PF) {
        #pragma unroll
        for (int k = 0; k < PF; k++) {
            int t = to + k;
            float4 v = buf[k];
            if (t + PF < T_)                       // refill slot (stays PF ahead)
                buf[k] = embv[ibase + (long)(t + PF) * stride];

            unsigned int m = s_meta[t];
            if (m & 1u) {
                acc.x += v.x; acc.y += v.y; acc.z += v.z; acc.w += v.w;
            }
            if (t >= L && active)
                outv[obase + (long)t * stride] = v;

            unsigned int e = m >> 1;
            if (e && active) {
                outv[obase + (long)((int)e - 1) * stride] = acc;
                acc = make_float4(0.f, 0.f, 0.f, 0.f);
            }
        }
    }
}

// ---------------------------------------------------------------------------
extern "C" void kernel_launch(void* const* d_in, const int* in_sizes, int n_in,
                              void* d_out, int out_size)
{
    const float* emb           = (const float*)d_in[0];   // (T,B,D) fp32
    const int*   src           = (const int*)d_in[1];     // (T,B) int32
    // d_in[2] = lengths (unused by reference computation)
    const int*   token_lengths = (const int*)d_in[3];     // (VOCAB,) int32
    const int*   token_len_p   = (n_in >= 5) ? (const int*)d_in[4] : nullptr;

    float* out = (float*)d_out;
    const long emb_elems = (long)T_ * B_ * D_;
    int write_len = (out_size >= emb_elems + B_) ? 1 : 0;

    setup_kernel<<<B_ / CPB, 128>>>(src, token_lengths, token_len_p);
    merge_kernel<<<B_, T_>>>((const float4*)emb, (float4*)out,
                             out + emb_elems, write_len);
}

// round 14
// speedup vs baseline: 1.3381x; 1.3381x over previous
#include <cuda_runtime.h>
#include <cuda_bf16.h>

#define T_ 128
#define B_ 512
#define D_ 500
#define D4_ 125   // D/4 float4 per row
#define PF 8      // prefetch depth (rows ahead)

// Scratch (no allocation allowed): control-plane metadata.
// g_meta[b*T_+t]: bit0 = token t valid; bits[1:15] = (seg_to_emit_after_t + 1), 0 = none.
__device__ unsigned short g_meta[B_ * T_];
__device__ int g_newlen[B_];

// ---------------------------------------------------------------------------
// Kernel 1: per-column greedy packing scan (control plane). Exact R12 body,
// plus an early PDL trigger so the merge kernel can launch and run its
// independent prologue (embv prefetch issue) concurrently with these scans.
// ---------------------------------------------------------------------------
__global__ __launch_bounds__(T_) void setup_kernel(const int* __restrict__ src,
                                                   const int* __restrict__ token_lengths,
                                                   const int* __restrict__ token_len_p)
{
    // Allow the dependent merge_kernel to begin launching now. Safe: setup's
    // 512 tiny blocks are all resident immediately (no deadlock), and merge
    // waits at cudaGridDependencySynchronize() before reading our outputs.
    cudaTriggerProgrammaticLaunchCompletion();

    __shared__ unsigned char  s_len[T_];
    __shared__ unsigned short s_meta[T_];

    int b = blockIdx.x;
    int t = threadIdx.x;

    // Parallel gather phase.
    int s = __ldcg(&src[t * B_ + b]);
    int l = (s == 1) ? 0 : ((s == 0) ? 4 : token_lengths[s]);
    s_len[t]  = (unsigned char)l;
    s_meta[t] = 0;
    __syncthreads();

    if (t == 0) {
        int token_len = token_len_p ? token_len_p[0] : 20;

        const uint4* p4 = (const uint4*)s_len;
        int seg = 0, curr = 0, last_t = 0;

        uint4 cur = p4[0];
        for (int k = 0; k < T_ / 16; k++) {      // NOT unrolled: compact body
            uint4 nxt = (k < T_ / 16 - 1) ? p4[k + 1] : cur;   // one-ahead prefetch
            uint wa0 = cur.x, wa1 = cur.y, wa2 = cur.z, wa3 = cur.w;
            #pragma unroll
            for (int q = 0; q < 16; q++) {       // compile-time indices only
                uint word = (q < 4) ? wa0 : (q < 8) ? wa1 : (q < 12) ? wa2 : wa3;
                int ll = (word >> ((q & 3) * 8)) & 0xFF;
                int tt = k * 16 + q;
                bool valid = (ll != 0);
                bool close = valid & (curr > 0) & (curr + ll > token_len);
                if (close) s_meta[last_t] |= (unsigned short)((seg + 1) << 1);
                seg  += (int)close;
                curr  = close ? 0 : curr;
                if (valid) s_meta[tt] |= 1;
                curr  += valid ? ll : 0;
                last_t = valid ? tt : last_t;
            }
            cur = nxt;
        }
        bool trail = (curr > 0);
        if (trail) s_meta[last_t] |= (unsigned short)((seg + 1) << 1);
        seg += (int)trail;
        g_newlen[b] = seg;
    }
    __syncthreads();

    // Cooperative writeback of metadata.
    g_meta[b * T_ + t] = s_meta[t];
}

// ---------------------------------------------------------------------------
// Kernel 2 (data plane + rank): one block per SOURCE column b, 128 threads.
// Exact R12 streaming body (37.1us, DRAM 70.8%). Launched with PDL: starts
// during setup, issues its setup-independent prefetches, then waits on
// cudaGridDependencySynchronize() before touching g_meta / g_newlen.
// Traffic: 262 MB total (each input row read once, each output row written once).
// ---------------------------------------------------------------------------
__global__ __launch_bounds__(T_) void merge_kernel(const float4* __restrict__ embv,
                                                   float4* __restrict__ outv,
                                                   float* __restrict__ out_len,
                                                   int write_len)
{
    __shared__ unsigned short s_meta[T_];
    __shared__ int s_warp[4];
    __shared__ int s_rank;

    int b = blockIdx.x;
    int i = threadIdx.x;

    const long stride = (long)B_ * D4_;        // float4s per t-slab
    bool active = (i < D4_);
    int  ic     = active ? i : (D4_ - 1);      // clamped: loads always valid
    long ibase  = (long)b * D4_ + ic;

    // ---- setup-independent prologue: kick off prefetch pipeline ----
    float4 buf[PF];
    #pragma unroll
    for (int k = 0; k < PF; k++) buf[k] = embv[ibase + (long)k * stride];

    // ---- wait for setup_kernel's results to be visible ----
    cudaGridDependencySynchronize();

    // ---- meta load + rank reduction (prefetches still in flight) ----
    s_meta[i] = g_meta[b * T_ + i];

    int myl = g_newlen[b];
    const int4* len4 = (const int4*)g_newlen;  // 512 / 4 = 128 == blockDim
    int4 v4 = len4[i];
    int j = 4 * i;
    int cnt = 0;
    cnt += (v4.x > myl) || (v4.x == myl && (j + 0) < b);
    cnt += (v4.y > myl) || (v4.y == myl && (j + 1) < b);
    cnt += (v4.z > myl) || (v4.z == myl && (j + 2) < b);
    cnt += (v4.w > myl) || (v4.w == myl && (j + 3) < b);
    #pragma unroll
    for (int o = 16; o > 0; o >>= 1) cnt += __shfl_down_sync(0xFFFFFFFFu, cnt, o);
    if ((i & 31) == 0) s_warp[i >> 5] = cnt;
    __syncthreads();
    if (i == 0) {
        int rank = s_warp[0] + s_warp[1] + s_warp[2] + s_warp[3];
        s_rank = rank;
        if (write_len) out_len[rank] = (float)myl;
    }
    __syncthreads();

    int  bo    = s_rank;
    int  L     = myl;
    long obase = (long)bo * D4_ + i;

    // ---- streaming loop with 8-deep ring buffer ----
    float4 acc = make_float4(0.f, 0.f, 0.f, 0.f);

    for (int to = 0; to < T_; to += PF) {
        #pragma unroll
        for (int k = 0; k < PF; k++) {
            int t = to + k;
            float4 v = buf[k];
            if (t + PF < T_)                       // refill slot (stays PF ahead)
                buf[k] = embv[ibase + (long)(t + PF) * stride];

            unsigned int m = s_meta[t];
            if (m & 1u) {
                acc.x += v.x; acc.y += v.y; acc.z += v.z; acc.w += v.w;
            }
            if (t >= L && active)
                outv[obase + (long)t * stride] = v;

            unsigned int e = m >> 1;
            if (e && active) {
                outv[obase + (long)((int)e - 1) * stride] = acc;
                acc = make_float4(0.f, 0.f, 0.f, 0.f);
            }
        }
    }
}

// ---------------------------------------------------------------------------
extern "C" void kernel_launch(void* const* d_in, const int* in_sizes, int n_in,
                              void* d_out, int out_size)
{
    const float* emb           = (const float*)d_in[0];   // (T,B,D) fp32
    const int*   src           = (const int*)d_in[1];     // (T,B) int32
    // d_in[2] = lengths (unused by reference computation)
    const int*   token_lengths = (const int*)d_in[3];     // (VOCAB,) int32
    const int*   token_len_p   = (n_in >= 5) ? (const int*)d_in[4] : nullptr;

    float* out = (float*)d_out;
    const long emb_elems = (long)T_ * B_ * D_;
    int write_len = (out_size >= emb_elems + B_) ? 1 : 0;

    setup_kernel<<<B_, T_>>>(src, token_lengths, token_len_p);

    // Merge launched with programmatic dependent launch: it may begin while
    // setup is still running; it synchronizes in-kernel before reading
    // setup's outputs.
    cudaLaunchConfig_t cfg = {};
    cfg.gridDim  = dim3(B_, 1, 1);
    cfg.blockDim = dim3(T_, 1, 1);
    cfg.dynamicSmemBytes = 0;
    cudaLaunchAttribute attrs[1];
    attrs[0].id = cudaLaunchAttributeProgrammaticStreamSerialization;
    attrs[0].val.programmaticStreamSerializationAllowed = 1;
    cfg.attrs = attrs;
    cfg.numAttrs = 1;
    cudaLaunchKernelEx(&cfg, merge_kernel,
                       (const float4*)emb, (float4*)out,
                       out + emb_elems, write_len);
}